// round 1
// baseline (speedup 1.0000x reference)
#include <cuda_runtime.h>

// ROICrop: bilinear crop of 1024 ROIs from a (4,256,200,304) fp32 source into
// (1024,256,14,14) fp32 output, with keep-aspect-ratio ROI adjustment (AR=1)
// and 10% extension, matching the JAX reference bit-for-fp32-bit in structure.
//
// Strategy: HBM-bound kernel. One block per ROI, thread = output pixel.
// Geometry (offsets + weights) hoisted out of the 256-channel loop; channel
// loop is 4 cached loads + FMA + 1 streaming store. All 1024 blocks are
// resident in one wave, so they sweep channels ~in lockstep and each 973 KB
// channel slice stays L2-resident across all overlapping ROIs.

#define SRC_N 4
#define SRC_C 256
#define SRC_H 200
#define SRC_W 304
#define SRC_HW (SRC_H * SRC_W)
#define OH 14
#define OW 14
#define OPIX (OH * OW)

__global__ __launch_bounds__(224, 8) void ROICrop_kernel(
    const float* __restrict__ src,
    const float* __restrict__ rois,
    float* __restrict__ out)
{
    const int roi = blockIdx.x;
    const int p = threadIdx.x;
    if (p >= OPIX) return;

    const int oy = p / OW;
    const int ox = p - oy * OW;

    // ---- load + adjust ROI (redundant per-thread; 5 broadcast loads, ~20 flops) ----
    const float* r = rois + roi * 5;
    const int b = (int)r[0];
    float x1 = r[1], y1 = r[2], x2 = r[3], y2 = r[4];

    // keep-aspect-ratio, AR = OW/OH = 1
    {
        const float h = y2 - y1 + 1.0f;
        const float w = x2 - x1 + 1.0f;
        const float ew = (h - w) * 0.5f;   // (h*AR - w)/2 with AR=1
        if (ew > 0.0f) {
            x1 -= ew; x2 += ew;
        } else {
            const float eh = (w - h) * 0.5f; // (w/AR - h)/2
            y1 -= eh; y2 += eh;
        }
    }
    // extend ratio 0.1
    {
        const float dx = (x2 - x1 + 1.0f) * 0.05f;
        const float dy = (y2 - y1 + 1.0f) * 0.05f;
        x1 -= dx; x2 += dx;
        y1 -= dy; y2 += dy;
    }

    // ---- per-pixel sample position ----
    const float ty = (float)oy / (float)(OH - 1);
    const float tx = (float)ox / (float)(OW - 1);
    float ys = y1 + (y2 - y1) * ty;
    float xs = x1 + (x2 - x1) * tx;
    ys = fminf(fmaxf(ys, 0.0f), (float)(SRC_H - 1));
    xs = fminf(fmaxf(xs, 0.0f), (float)(SRC_W - 1));

    const float y0f = floorf(ys);
    const float x0f = floorf(xs);
    const float wy = ys - y0f;
    const float wx = xs - x0f;
    const int y0 = (int)y0f;
    const int x0 = (int)x0f;
    const int y1i = min(y0 + 1, SRC_H - 1);
    const int x1i = min(x0 + 1, SRC_W - 1);

    const int o00 = y0  * SRC_W + x0;
    const int o01 = y0  * SRC_W + x1i;
    const int o10 = y1i * SRC_W + x0;
    const int o11 = y1i * SRC_W + x1i;

    const float w00 = (1.0f - wy) * (1.0f - wx);
    const float w01 = (1.0f - wy) * wx;
    const float w10 = wy * (1.0f - wx);
    const float w11 = wy * wx;

    const float* base = src + (size_t)b * SRC_C * SRC_HW;
    float* outp = out + (size_t)roi * SRC_C * OPIX + p;

    // ---- channel loop: 4 loads + 4 FMA + 1 streaming store per iteration ----
#pragma unroll 4
    for (int c = 0; c < SRC_C; ++c) {
        const float* s = base + (size_t)c * SRC_HW;
        float v = w00 * __ldg(s + o00)
                + w01 * __ldg(s + o01)
                + w10 * __ldg(s + o10)
                + w11 * __ldg(s + o11);
        __stcs(outp + (size_t)c * OPIX, v);
    }
}

extern "C" void kernel_launch(void* const* d_in, const int* in_sizes, int n_in,
                              void* d_out, int out_size)
{
    const float* src  = (const float*)d_in[0];
    const float* rois = (const float*)d_in[1];
    float* out = (float*)d_out;

    const int n_rois = in_sizes[1] / 5;   // 1024
    ROICrop_kernel<<<n_rois, 224>>>(src, rois, out);
}

// round 4
// speedup vs baseline: 1.4446x; 1.4446x over previous
#include <cuda_runtime.h>

// ROICrop: bilinear crop of 1024 ROIs from (4,256,200,304) fp32 source into
// (1024,256,14,14) fp32 output. KEEP_AR (AR=1) + 10% extend ROI adjustment.
//
// R4 strategy: same optimization as R2/R3 (channel banding for occupancy +
// L2 residency) but expressed on a 1D grid — the 2D grid is the only
// structural delta from the R1 kernel that passed, and the banded kernel
// container-failed twice, so the 2D launch is the prime suspect.
//
//  - 8192 blocks (= 8 bands x 1024 ROIs) -> ~7 waves, full occupancy
//  - block = band * n_rois + roi, so roi is the fastest-varying index:
//    each dispatch wave works one ~31 MB channel band of all 4 images,
//    which is L2-resident -> source DRAM reads approach one pass (249 MB)
//  - unroll 8 over the 32-channel band -> ~32 outstanding loads per thread
//  - streaming stores (__stcs) keep the 205 MB output from evicting the
//    L2-resident source band

#define SRC_N 4
#define SRC_C 256
#define SRC_H 200
#define SRC_W 304
#define SRC_HW (SRC_H * SRC_W)
#define OH 14
#define OW 14
#define OPIX (OH * OW)
#define C_BANDS 8
#define C_PER_BAND (SRC_C / C_BANDS)   // 32

__global__ __launch_bounds__(224, 8) void ROICrop_kernel(
    const float* __restrict__ src,
    const float* __restrict__ rois,
    float* __restrict__ out,
    int n_rois)
{
    const int bid = blockIdx.x;
    const int roi  = bid % n_rois;          // fastest-varying: wave = one band
    const int band = bid / n_rois;
    const int c0 = band * C_PER_BAND;
    const int p = threadIdx.x;
    if (p >= OPIX) return;

    const int oy = p / OW;
    const int ox = p - oy * OW;

    // ---- load + adjust ROI (redundant per-thread; broadcast loads) ----
    const float* r = rois + roi * 5;
    const int b = (int)r[0];
    float x1 = r[1], y1 = r[2], x2 = r[3], y2 = r[4];

    // keep-aspect-ratio, AR = OW/OH = 1
    {
        const float h = y2 - y1 + 1.0f;
        const float w = x2 - x1 + 1.0f;
        const float ew = (h - w) * 0.5f;     // (h*AR - w)/2 with AR=1
        if (ew > 0.0f) {
            x1 -= ew; x2 += ew;
        } else {
            const float eh = (w - h) * 0.5f; // (w/AR - h)/2
            y1 -= eh; y2 += eh;
        }
    }
    // extend ratio 0.1
    {
        const float dx = (x2 - x1 + 1.0f) * 0.05f;
        const float dy = (y2 - y1 + 1.0f) * 0.05f;
        x1 -= dx; x2 += dx;
        y1 -= dy; y2 += dy;
    }

    // ---- per-pixel sample position ----
    const float ty = (float)oy / (float)(OH - 1);
    const float tx = (float)ox / (float)(OW - 1);
    float ys = y1 + (y2 - y1) * ty;
    float xs = x1 + (x2 - x1) * tx;
    ys = fminf(fmaxf(ys, 0.0f), (float)(SRC_H - 1));
    xs = fminf(fmaxf(xs, 0.0f), (float)(SRC_W - 1));

    const float y0f = floorf(ys);
    const float x0f = floorf(xs);
    const float wy = ys - y0f;
    const float wx = xs - x0f;
    const int y0 = (int)y0f;
    const int x0 = (int)x0f;
    const int y1i = min(y0 + 1, SRC_H - 1);
    const int x1i = min(x0 + 1, SRC_W - 1);

    const int o00 = y0  * SRC_W + x0;
    const int o01 = y0  * SRC_W + x1i;
    const int o10 = y1i * SRC_W + x0;
    const int o11 = y1i * SRC_W + x1i;

    const float w00 = (1.0f - wy) * (1.0f - wx);
    const float w01 = (1.0f - wy) * wx;
    const float w10 = wy * (1.0f - wx);
    const float w11 = wy * wx;

    const float* base = src + (size_t)b * SRC_C * SRC_HW + (size_t)c0 * SRC_HW;
    float* outp = out + (size_t)roi * SRC_C * OPIX + (size_t)c0 * OPIX + p;

    // ---- channel-band loop: 4 loads + 4 FMA + 1 streaming store per iter ----
#pragma unroll 8
    for (int c = 0; c < C_PER_BAND; ++c) {
        const float* s = base + (size_t)c * SRC_HW;
        float v = w00 * __ldg(s + o00)
                + w01 * __ldg(s + o01)
                + w10 * __ldg(s + o10)
                + w11 * __ldg(s + o11);
        __stcs(outp + (size_t)c * OPIX, v);
    }
}

extern "C" void kernel_launch(void* const* d_in, const int* in_sizes, int n_in,
                              void* d_out, int out_size)
{
    const float* src  = (const float*)d_in[0];
    const float* rois = (const float*)d_in[1];
    float* out = (float*)d_out;

    int n_rois = in_sizes[1] / 5;   // 1024
    if (n_rois < 1) n_rois = 1;
    ROICrop_kernel<<<n_rois * C_BANDS, 224>>>(src, rois, out, n_rois);
}